// round 2
// baseline (speedup 1.0000x reference)
#include <cuda_runtime.h>
#include <cstdint>

#define N_NODES 100000
#define N_EDGES 1600000
#define C 32

#define SCAN_CHUNK 1024
#define NBLK ((N_NODES + SCAN_CHUNK - 1) / SCAN_CHUNK)   // 98

// Scratch (static device globals; allocation is forbidden)
__device__ int   g_degi[N_NODES];            // in-degree histogram (no self loop)
__device__ int   g_rowptr[N_NODES];          // CSR start offsets (exclusive scan)
__device__ int   g_cursor[N_NODES];          // fill cursors; == end offsets after fill
__device__ int   g_bsum[NBLK];
__device__ int   g_boff[NBLK];
__device__ int   g_elist[N_EDGES];           // source node per binned edge
__device__ float g_dinv[N_NODES];
__device__ float g_hs[N_NODES * C];          // hs[i] = (x[i] @ W^T) * dinv[i]

// ---------------------------------------------------------------------------
// K0: zero the histogram
__global__ void k_zero() {
    int i = blockIdx.x * blockDim.x + threadIdx.x;
    if (i < N_NODES) g_degi[i] = 0;
}

// K1: in-degree histogram over targets (4 edges per thread, vectorized load)
__global__ void k_hist(const int* __restrict__ col) {
    int t = blockIdx.x * blockDim.x + threadIdx.x;
    int e4 = t * 4;
    if (e4 + 3 < N_EDGES) {
        int4 c = *reinterpret_cast<const int4*>(col + e4);
        atomicAdd(&g_degi[c.x], 1);
        atomicAdd(&g_degi[c.y], 1);
        atomicAdd(&g_degi[c.z], 1);
        atomicAdd(&g_degi[c.w], 1);
    } else {
        for (int e = e4; e < N_EDGES; e++) atomicAdd(&g_degi[col[e]], 1);
    }
}

// K2a: per-block exclusive scan (Hillis-Steele), block totals to g_bsum
__global__ void k_scan1() {
    __shared__ int sh[SCAN_CHUNK];
    int tid = threadIdx.x;
    int gid = blockIdx.x * SCAN_CHUNK + tid;
    int v = (gid < N_NODES) ? g_degi[gid] : 0;
    sh[tid] = v;
    __syncthreads();
    #pragma unroll
    for (int off = 1; off < SCAN_CHUNK; off <<= 1) {
        int t = (tid >= off) ? sh[tid - off] : 0;
        __syncthreads();
        sh[tid] += t;
        __syncthreads();
    }
    if (gid < N_NODES) g_rowptr[gid] = sh[tid] - v;   // exclusive (local)
    if (tid == SCAN_CHUNK - 1) g_bsum[blockIdx.x] = sh[tid];
}

// K2b: scan the 98 block totals (single block of 128)
__global__ void k_scan2() {
    __shared__ int sh[128];
    int tid = threadIdx.x;
    int v = (tid < NBLK) ? g_bsum[tid] : 0;
    sh[tid] = v;
    __syncthreads();
    #pragma unroll
    for (int off = 1; off < 128; off <<= 1) {
        int t = (tid >= off) ? sh[tid - off] : 0;
        __syncthreads();
        sh[tid] += t;
        __syncthreads();
    }
    if (tid < NBLK) g_boff[tid] = sh[tid] - v;   // exclusive
}

// K2c: add block offsets; initialize cursors
__global__ void k_scan3() {
    int gid = blockIdx.x * SCAN_CHUNK + threadIdx.x;
    if (gid < N_NODES) {
        int p = g_rowptr[gid] + g_boff[blockIdx.x];
        g_rowptr[gid] = p;
        g_cursor[gid] = p;
    }
}

// K3: bin edges by target: elist[cursor[col]++] = row
__global__ void k_fill(const int* __restrict__ rowv, const int* __restrict__ colv) {
    int e = blockIdx.x * blockDim.x + threadIdx.x;
    if (e < N_EDGES) {
        int c = __ldg(colv + e);
        int pos = atomicAdd(&g_cursor[c], 1);
        g_elist[pos] = __ldg(rowv + e);
    }
}

// K4: dinv = rsqrt(deg+1); hs = (x @ W^T) * dinv
// Block = 256 threads = 8 nodes x 32 output channels.
__global__ void k_gemm(const float* __restrict__ x, const float* __restrict__ W) {
    __shared__ float Wsh[C][C + 1];   // Wsh[k][co] = W[co*C + k]
    int tid = threadIdx.x;
    #pragma unroll
    for (int i = tid; i < C * C; i += 256) {
        Wsh[i % C][i / C] = W[i];
    }
    __syncthreads();

    int n  = blockIdx.x * 8 + (tid >> 5);
    int co = tid & 31;
    if (n >= N_NODES) return;

    float dinv = rsqrtf((float)(g_degi[n] + 1));   // +1 = self loop
    if (co == 0) g_dinv[n] = dinv;

    const float* xr = x + n * C;
    float acc = 0.0f;
    #pragma unroll
    for (int k = 0; k < C; k++) acc += __ldg(xr + k) * Wsh[k][co];
    g_hs[n * C + co] = acc * dinv;
}

// K5: atomic-free gather. Warp per node, lane = channel.
//     out[n] = dinv[n] * ( hs[n] + sum_{e in-edges} hs[src(e)] ) + b
__global__ void k_gather(float* __restrict__ out, const float* __restrict__ b) {
    int n = blockIdx.x * 8 + (threadIdx.x >> 5);
    int lane = threadIdx.x & 31;
    if (n >= N_NODES) return;

    int start = g_rowptr[n];
    int end   = g_cursor[n];       // == rowptr[n] + deg_in[n] after fill
    float acc = g_hs[n * C + lane];   // self-loop term

    int i = start;
    for (; i + 4 <= end; i += 4) {
        int r0 = __ldg(g_elist + i);
        int r1 = __ldg(g_elist + i + 1);
        int r2 = __ldg(g_elist + i + 2);
        int r3 = __ldg(g_elist + i + 3);
        float v0 = __ldg(g_hs + r0 * C + lane);
        float v1 = __ldg(g_hs + r1 * C + lane);
        float v2 = __ldg(g_hs + r2 * C + lane);
        float v3 = __ldg(g_hs + r3 * C + lane);
        acc += v0; acc += v1; acc += v2; acc += v3;
    }
    for (; i < end; i++) {
        int r = __ldg(g_elist + i);
        acc += __ldg(g_hs + r * C + lane);
    }

    out[n * C + lane] = acc * g_dinv[n] + __ldg(b + lane);
}

// ---------------------------------------------------------------------------
extern "C" void kernel_launch(void* const* d_in, const int* in_sizes, int n_in,
                              void* d_out, int out_size) {
    const float* x  = (const float*)d_in[0];
    const int*   ei = (const int*)d_in[1];    // [2, E]: row then col
    const float* W  = (const float*)d_in[2];
    const float* b  = (const float*)d_in[3];
    float* out = (float*)d_out;

    const int* rowv = ei;
    const int* colv = ei + N_EDGES;

    k_zero<<<(N_NODES + 255) / 256, 256>>>();
    k_hist<<<(N_EDGES / 4 + 255) / 256, 256>>>(colv);
    k_scan1<<<NBLK, SCAN_CHUNK>>>();
    k_scan2<<<1, 128>>>();
    k_scan3<<<NBLK, SCAN_CHUNK>>>();
    k_fill<<<(N_EDGES + 255) / 256, 256>>>(rowv, colv);
    k_gemm<<<(N_NODES + 7) / 8, 256>>>(x, W);
    k_gather<<<(N_NODES + 7) / 8, 256>>>(out, b);
}